// round 2
// baseline (speedup 1.0000x reference)
#include <cuda_runtime.h>
#include <cuda_bf16.h>
#include <math.h>

// Problem constants
#define B_DIM 16
#define Z_DIM 64
#define U_DIM 8
#define P_DIM 128
#define X_DIM 64
#define H_DIM 128
#define NTILES (B_DIM * Z_DIM * U_DIM)   // 8192

// Scratch for phi = encoder(x): (B, H) floats. No cudaMalloc allowed.
__device__ float g_phi[B_DIM * H_DIM];

// ---------------------------------------------------------------------------
// Kernel 1: 4-layer MLP encoder. One block per batch row, 128 threads.
// phi = ((elu(elu(elu(x@W1+b1)@W2+b2)@W3+b3))@W4 + b4)
// ---------------------------------------------------------------------------
__global__ void encoder_kernel(const float* __restrict__ x,
                               const float* __restrict__ W1, const float* __restrict__ b1,
                               const float* __restrict__ W2, const float* __restrict__ b2,
                               const float* __restrict__ W3, const float* __restrict__ b3,
                               const float* __restrict__ W4, const float* __restrict__ b4) {
    __shared__ float buf0[H_DIM];
    __shared__ float buf1[H_DIM];
    const int b = blockIdx.x;
    const int j = threadIdx.x;   // 0..127

    if (j < X_DIM) buf0[j] = x[b * X_DIM + j];
    __syncthreads();

    // Layer 1: X_DIM -> H_DIM, ELU
    float s = b1[j];
#pragma unroll 8
    for (int k = 0; k < X_DIM; ++k) s += buf0[k] * W1[k * H_DIM + j];
    buf1[j] = (s > 0.0f) ? s : expm1f(s);
    __syncthreads();

    // Layer 2: H -> H, ELU
    s = b2[j];
#pragma unroll 8
    for (int k = 0; k < H_DIM; ++k) s += buf1[k] * W2[k * H_DIM + j];
    buf0[j] = (s > 0.0f) ? s : expm1f(s);
    __syncthreads();

    // Layer 3: H -> H, ELU
    s = b3[j];
#pragma unroll 8
    for (int k = 0; k < H_DIM; ++k) s += buf0[k] * W3[k * H_DIM + j];
    buf1[j] = (s > 0.0f) ? s : expm1f(s);
    __syncthreads();

    // Layer 4: H -> P, linear
    s = b4[j];
#pragma unroll 8
    for (int k = 0; k < H_DIM; ++k) s += buf1[k] * W4[k * P_DIM + j];
    g_phi[b * H_DIM + j] = s;
}

// ---------------------------------------------------------------------------
// Kernel 2: per (b,z,u) tile, stream L = Linv[b,z,u] (128x128 f32 = 64KB):
//   mu    = phi^T L q2     (folds K = einsum(Q2, Linv) and mu = einsum(K, phi))
//   sigma = phi^T L phi
//   out[tile]        = mu
//   out[8192 + tile] = exp(logSigEps[u]) * (1 + sigma)
//
// 256 threads/block. Thread layout: lane owns a fixed column quad
//   col = (tid & 31) * 4   (q2/phi at col held in registers for whole tile)
// and iterates rows row = 8*i + (tid >> 5), i = 0..15 — 16 independent
// float4 loads per thread, warp-contiguous 512B transactions.
// ---------------------------------------------------------------------------
__global__ __launch_bounds__(256)
void tile_kernel(const float* __restrict__ Linv,
                 const float* __restrict__ Q,
                 const float* __restrict__ logSigEps,
                 float* __restrict__ out) {
    const int tile = blockIdx.x;            // (b*Z + z)*U + u
    const int b    = tile >> 9;             // / (Z*U) = /512
    const int u    = tile & (U_DIM - 1);

    const float* __restrict__ L  = Linv + (size_t)tile * (P_DIM * P_DIM);
    const float* __restrict__ q2 = Q    + (size_t)tile * P_DIM;

    __shared__ float phi_s[P_DIM];
    __shared__ float red_mu[8];
    __shared__ float red_sig[8];

    const int tid  = threadIdx.x;
    const int lane = tid & 31;
    const int wid  = tid >> 5;              // 0..7

    if (tid < P_DIM) phi_s[tid] = g_phi[b * H_DIM + tid];
    __syncthreads();

    const int col = lane * 4;
    const float4 qc = __ldg(reinterpret_cast<const float4*>(q2 + col));
    const float4 pc = *reinterpret_cast<const float4*>(&phi_s[col]);

    float mu = 0.0f, sig = 0.0f;

#pragma unroll
    for (int i = 0; i < 16; ++i) {
        const int row = i * 8 + wid;
        const float pr = phi_s[row];
        const float4 l = __ldcs(reinterpret_cast<const float4*>(L + (size_t)row * P_DIM + col));
        const float d1 = l.x * qc.x + l.y * qc.y + l.z * qc.z + l.w * qc.w;
        const float d2 = l.x * pc.x + l.y * pc.y + l.z * pc.z + l.w * pc.w;
        mu  = fmaf(pr, d1, mu);
        sig = fmaf(pr, d2, sig);
    }

    // warp reduction
#pragma unroll
    for (int o = 16; o > 0; o >>= 1) {
        mu  += __shfl_xor_sync(0xffffffffu, mu,  o);
        sig += __shfl_xor_sync(0xffffffffu, sig, o);
    }
    if (lane == 0) { red_mu[wid] = mu; red_sig[wid] = sig; }
    __syncthreads();

    if (tid == 0) {
        float m = 0.0f, s = 0.0f;
#pragma unroll
        for (int w = 0; w < 8; ++w) { m += red_mu[w]; s += red_sig[w]; }
        out[tile]          = m;
        out[NTILES + tile] = expf(logSigEps[u]) * (1.0f + s);
    }
}

// ---------------------------------------------------------------------------
// kernel_launch
// Input order (metadata): x, Linv, Q, W1, b1, W2, b2, W3, b3, W4, b4, logSigEps
// Output: [mu (8192 floats) | pred_cov_diag (8192 floats)]
// ---------------------------------------------------------------------------
extern "C" void kernel_launch(void* const* d_in, const int* in_sizes, int n_in,
                              void* d_out, int out_size) {
    (void)in_sizes; (void)n_in; (void)out_size;
    const float* x         = (const float*)d_in[0];
    const float* Linv      = (const float*)d_in[1];
    const float* Q         = (const float*)d_in[2];
    const float* W1        = (const float*)d_in[3];
    const float* b1        = (const float*)d_in[4];
    const float* W2        = (const float*)d_in[5];
    const float* b2        = (const float*)d_in[6];
    const float* W3        = (const float*)d_in[7];
    const float* b3        = (const float*)d_in[8];
    const float* W4        = (const float*)d_in[9];
    const float* b4        = (const float*)d_in[10];
    const float* logSigEps = (const float*)d_in[11];
    float* out = (float*)d_out;

    encoder_kernel<<<B_DIM, H_DIM>>>(x, W1, b1, W2, b2, W3, b3, W4, b4);
    tile_kernel<<<NTILES, 256>>>(Linv, Q, logSigEps, out);
}